// round 5
// baseline (speedup 1.0000x reference)
#include <cuda_runtime.h>
#include <math.h>

// Problem constants
#define B_BATCH   32
#define NPTS      65536
#define NCH       14
#define CHUNKS    64
#define ROWS_PER_BLOCK (NPTS / CHUNKS)             // 1024
#define THREADS   256
#define ROWS_PER_THREAD (ROWS_PER_BLOCK / THREADS) // 4
#define TOTAL_BLOCKS (B_BATCH * CHUNKS)            // 2048

#define EPS_D       1e-06
#define MAX_RATIO_D 1000000.0
#define CLAMP_ABS_D 1000000.0

// Per-(batch,chunk) partial moments (static scratch; no allocation)
__device__ float        g_part[B_BATCH * CHUNKS * 9];
__device__ unsigned int g_done = 0;   // self-resetting completion counter

__device__ __forceinline__ double sanitize_d(double v)
{
    if (isnan(v)) return 0.0;
    if (v >  CLAMP_ABS_D) return  CLAMP_ABS_D;
    if (v < -CLAMP_ABS_D) return -CLAMP_ABS_D;
    return v;
}

// ---------------------------------------------------------------------------
// Fused kernel: each block accumulates 9 raw moments for one (batch, chunk);
// the LAST block to finish performs the cross-chunk reduction, covariance,
// closed-form symmetric 3x3 eigenvalues, and the final loss.
// Deterministic: fixed per-thread serial order, fixed tree reductions, and
// the finalize sums the partial array in a fixed order (independent of which
// block happens to be last).
// ---------------------------------------------------------------------------
__global__ __launch_bounds__(THREADS)
void pcl_fused_kernel(const float* __restrict__ g, float* __restrict__ out)
{
    const int chunk = blockIdx.x;
    const int b     = blockIdx.y;
    const int tid   = threadIdx.x;

    const float* base = g + ((size_t)b * NPTS + (size_t)chunk * ROWS_PER_BLOCK) * NCH;

    // ---- Phase 1: per-block moment accumulation (HBM-bound) ----
    // Row start = 56*i bytes -> always 8-byte aligned: float2 (x,y) + scalar z.
    float x[ROWS_PER_THREAD], y[ROWS_PER_THREAD], z[ROWS_PER_THREAD];
#pragma unroll
    for (int k = 0; k < ROWS_PER_THREAD; k++) {
        const float* r = base + (size_t)(k * THREADS + tid) * NCH;
        const float2 xy = *(const float2*)r;
        x[k] = xy.x;
        y[k] = xy.y;
        z[k] = __ldg(r + 2);
    }

    float sx = 0.f, sy = 0.f, sz = 0.f;
    float sxx = 0.f, sxy = 0.f, sxz = 0.f, syy = 0.f, syz = 0.f, szz = 0.f;
#pragma unroll
    for (int k = 0; k < ROWS_PER_THREAD; k++) {
        sx += x[k]; sy += y[k]; sz += z[k];
        sxx = fmaf(x[k], x[k], sxx);
        sxy = fmaf(x[k], y[k], sxy);
        sxz = fmaf(x[k], z[k], sxz);
        syy = fmaf(y[k], y[k], syy);
        syz = fmaf(y[k], z[k], syz);
        szz = fmaf(z[k], z[k], szz);
    }

    float v[9] = { sx, sy, sz, sxx, sxy, sxz, syy, syz, szz };

    // Warp tree reduce (deterministic)
#pragma unroll
    for (int o = 16; o > 0; o >>= 1) {
#pragma unroll
        for (int i = 0; i < 9; i++)
            v[i] += __shfl_down_sync(0xffffffffu, v[i], o);
    }

    __shared__ float sm[8][9];
    const int warp = tid >> 5, lane = tid & 31;
    if (lane == 0) {
#pragma unroll
        for (int i = 0; i < 9; i++) sm[warp][i] = v[i];
    }
    __syncthreads();

    if (warp == 0) {
        float w[9];
#pragma unroll
        for (int i = 0; i < 9; i++) w[i] = (lane < 8) ? sm[lane][i] : 0.f;
#pragma unroll
        for (int o = 4; o > 0; o >>= 1) {
#pragma unroll
            for (int i = 0; i < 9; i++)
                w[i] += __shfl_down_sync(0xffffffffu, w[i], o);
        }
        if (lane == 0) {
            float* dst = &g_part[(size_t)(b * CHUNKS + chunk) * 9];
#pragma unroll
            for (int i = 0; i < 9; i++) dst[i] = w[i];
        }
    }

    // ---- Completion counting: threadfence-reduction pattern ----
    // Writer of g_part is tid 0 (warp 0 / lane 0); tid 0 also issues the
    // fence and the atomic, so write -> fence -> atomic is program-ordered.
    __shared__ unsigned int s_rank;
    __threadfence();
    if (tid == 0) s_rank = atomicAdd(&g_done, 1u);
    __syncthreads();
    if (s_rank != TOTAL_BLOCKS - 1u) return;

    // Last block: reset counter for next graph replay (all other blocks done).
    if (tid == 0) g_done = 0;

    // ---- Phase 2: finalize (fixed order => deterministic) ----
    __shared__ double red[THREADS][9];   // 18 KB
    __shared__ double lr[B_BATCH];

    const int fb   = tid >> 3;   // batch 0..31
    const int part = tid & 7;    // 8 partial-summers per batch

    double a[9];
#pragma unroll
    for (int i = 0; i < 9; i++) a[i] = 0.0;
    for (int c = part; c < CHUNKS; c += 8) {
        const float* src = &g_part[(size_t)(fb * CHUNKS + c) * 9];
#pragma unroll
        for (int i = 0; i < 9; i++) a[i] += (double)src[i];
    }
#pragma unroll
    for (int i = 0; i < 9; i++) red[tid][i] = a[i];
    __syncthreads();

    for (int s = 4; s > 0; s >>= 1) {
        if (part < s) {
#pragma unroll
            for (int i = 0; i < 9; i++) red[tid][i] += red[tid + s][i];
        }
        __syncthreads();
    }

    if (part == 0) {
        const double invN = 1.0 / (double)NPTS;
        const double mx = red[tid][0] * invN;
        const double my = red[tid][1] * invN;
        const double mz = red[tid][2] * invN;

        const double c00 = sanitize_d(red[tid][3] * invN - mx * mx);
        const double c01 = sanitize_d(red[tid][4] * invN - mx * my);
        const double c02 = sanitize_d(red[tid][5] * invN - mx * mz);
        const double c11 = sanitize_d(red[tid][6] * invN - my * my);
        const double c12 = sanitize_d(red[tid][7] * invN - my * mz);
        const double c22 = sanitize_d(red[tid][8] * invN - mz * mz);
        // Already symmetric; 0.5*(C + C^T) is the identity here.

        // Closed-form eigenvalues: fp64 fixed-latency arithmetic only,
        // float transcendentals (error enters scaled by 2p ~ 1e-2).
        double emax, emin;
        const double p1 = c01 * c01 + c02 * c02 + c12 * c12;
        if (p1 == 0.0) {
            emax = fmax(c00, fmax(c11, c22));
            emin = fmin(c00, fmin(c11, c22));
        } else {
            const double q  = (c00 + c11 + c22) * (1.0 / 3.0);
            const double d0 = c00 - q, d1 = c11 - q, d2 = c22 - q;
            const double p2 = d0 * d0 + d1 * d1 + d2 * d2 + 2.0 * p1;
            const double p  = sqrt(p2 * (1.0 / 6.0));
            const double ip = 1.0 / p;
            const double b00 = d0 * ip, b11 = d1 * ip, b22 = d2 * ip;
            const double b01 = c01 * ip, b02 = c02 * ip, b12 = c12 * ip;
            double r = 0.5 * (b00 * (b11 * b22 - b12 * b12)
                            - b01 * (b01 * b22 - b12 * b02)
                            + b02 * (b01 * b12 - b11 * b02));
            r = fmin(1.0, fmax(-1.0, r));
            const float phi = acosf((float)r) * (1.0f / 3.0f);
            emax = q + 2.0 * p * (double)cosf(phi);
            emin = q + 2.0 * p * (double)cosf(phi + 2.0943951023931953f);
        }

        const double max_e = fmax(sanitize_d(emax), EPS_D);
        const double min_e = fmax(sanitize_d(emin), EPS_D);
        double ratio = max_e / min_e;
        ratio = fmin(MAX_RATIO_D, fmax(1.0, ratio));
        lr[fb] = (double)logf((float)ratio);
    }
    __syncthreads();

    if (tid == 0) {
        double s = 0.0;
#pragma unroll
        for (int i = 0; i < B_BATCH; i++) s += lr[i];
        out[0] = (float)(-s * (1.0 / (double)B_BATCH));
    }
}

// ---------------------------------------------------------------------------
extern "C" void kernel_launch(void* const* d_in, const int* in_sizes, int n_in,
                              void* d_out, int out_size)
{
    (void)in_sizes; (void)n_in; (void)out_size;
    const float* gaussians = (const float*)d_in[0];
    float* out = (float*)d_out;

    dim3 grid(CHUNKS, B_BATCH);
    pcl_fused_kernel<<<grid, THREADS>>>(gaussians, out);
}

// round 9
// speedup vs baseline: 1.4896x; 1.4896x over previous
#include <cuda_runtime.h>
#include <math.h>

// Problem constants
#define B_BATCH   32
#define NPTS      65536
#define NCH       14
#define CHUNKS    32
#define ROWS_PER_BLOCK (NPTS / CHUNKS)             // 2048
#define THREADS   256
#define ROWS_PER_THREAD (ROWS_PER_BLOCK / THREADS) // 8

#define EPS_D       1e-06
#define MAX_RATIO_D 1000000.0
#define CLAMP_ABS_D 1000000.0

// Per-(batch,chunk) partial moments (static scratch; no allocation)
__device__ float g_part[B_BATCH * CHUNKS * 9];

// ---------------------------------------------------------------------------
// Kernel 1 (HBM-bound): 9 raw moments per (batch, chunk) block.
// 8 rows/thread -> 16 independent LDGs in flight per thread for MLP.
// Deterministic: fixed per-thread order + fixed tree reduction.
// ---------------------------------------------------------------------------
__global__ __launch_bounds__(THREADS)
void moments_kernel(const float* __restrict__ g)
{
    const int chunk = blockIdx.x;
    const int b     = blockIdx.y;
    const int tid   = threadIdx.x;

    const float* __restrict__ base =
        g + ((size_t)b * NPTS + (size_t)chunk * ROWS_PER_BLOCK) * NCH;

    // Row start = 56B*i -> always 8-byte aligned: float2 (x,y) + scalar z.
    float x[ROWS_PER_THREAD], y[ROWS_PER_THREAD], z[ROWS_PER_THREAD];
#pragma unroll
    for (int k = 0; k < ROWS_PER_THREAD; k++) {
        const size_t off = (size_t)(k * THREADS + tid) * NCH;
        const float2 xy = *(const float2*)(base + off);
        x[k] = xy.x;
        y[k] = xy.y;
        z[k] = base[off + 2];
    }

    float sx = 0.f, sy = 0.f, sz = 0.f;
    float sxx = 0.f, sxy = 0.f, sxz = 0.f, syy = 0.f, syz = 0.f, szz = 0.f;
#pragma unroll
    for (int k = 0; k < ROWS_PER_THREAD; k++) {
        sx += x[k]; sy += y[k]; sz += z[k];
        sxx = fmaf(x[k], x[k], sxx);
        sxy = fmaf(x[k], y[k], sxy);
        sxz = fmaf(x[k], z[k], sxz);
        syy = fmaf(y[k], y[k], syy);
        syz = fmaf(y[k], z[k], syz);
        szz = fmaf(z[k], z[k], szz);
    }

    float v[9] = { sx, sy, sz, sxx, sxy, sxz, syy, syz, szz };

    // Warp tree reduce (deterministic)
#pragma unroll
    for (int o = 16; o > 0; o >>= 1) {
#pragma unroll
        for (int i = 0; i < 9; i++)
            v[i] += __shfl_down_sync(0xffffffffu, v[i], o);
    }

    __shared__ float sm[8][9];
    const int warp = tid >> 5, lane = tid & 31;
    if (lane == 0) {
#pragma unroll
        for (int i = 0; i < 9; i++) sm[warp][i] = v[i];
    }
    __syncthreads();

    if (warp == 0) {
        float w[9];
#pragma unroll
        for (int i = 0; i < 9; i++) w[i] = (lane < 8) ? sm[lane][i] : 0.f;
#pragma unroll
        for (int o = 4; o > 0; o >>= 1) {
#pragma unroll
            for (int i = 0; i < 9; i++)
                w[i] += __shfl_down_sync(0xffffffffu, w[i], o);
        }
        if (lane == 0) {
            float* dst = &g_part[(size_t)(b * CHUNKS + chunk) * 9];
#pragma unroll
            for (int i = 0; i < 9; i++) dst[i] = w[i];
        }
    }
}

// ---------------------------------------------------------------------------
// Kernel 2 (tiny): per-batch covariance -> closed-form symmetric 3x3
// eigenvalues (fp64 fixed-latency arithmetic, float transcendentals)
// -> -mean(log(clamp(max/min, 1, 1e6))).
// ---------------------------------------------------------------------------
__device__ __forceinline__ double sanitize_d(double v)
{
    if (isnan(v)) return 0.0;
    if (v >  CLAMP_ABS_D) return  CLAMP_ABS_D;
    if (v < -CLAMP_ABS_D) return -CLAMP_ABS_D;
    return v;
}

__global__ __launch_bounds__(THREADS)
void finalize_kernel(float* __restrict__ out)
{
    __shared__ double red[THREADS][9];   // 18 KB (single block; occupancy irrelevant)
    __shared__ double lr[B_BATCH];

    const int tid  = threadIdx.x;   // 256 = 32 batches x 8 partial-summers
    const int b    = tid >> 3;
    const int part = tid & 7;

    double a[9];
#pragma unroll
    for (int i = 0; i < 9; i++) a[i] = 0.0;
    // Fixed order per thread -> deterministic (4 chunks each)
    for (int c = part; c < CHUNKS; c += 8) {
        const float* src = &g_part[(size_t)(b * CHUNKS + c) * 9];
#pragma unroll
        for (int i = 0; i < 9; i++) a[i] += (double)src[i];
    }
#pragma unroll
    for (int i = 0; i < 9; i++) red[tid][i] = a[i];
    __syncthreads();

    for (int s = 4; s > 0; s >>= 1) {
        if (part < s) {
#pragma unroll
            for (int i = 0; i < 9; i++) red[tid][i] += red[tid + s][i];
        }
        __syncthreads();
    }

    if (part == 0) {
        const double invN = 1.0 / (double)NPTS;
        const double mx = red[tid][0] * invN;
        const double my = red[tid][1] * invN;
        const double mz = red[tid][2] * invN;

        const double c00 = sanitize_d(red[tid][3] * invN - mx * mx);
        const double c01 = sanitize_d(red[tid][4] * invN - mx * my);
        const double c02 = sanitize_d(red[tid][5] * invN - mx * mz);
        const double c11 = sanitize_d(red[tid][6] * invN - my * my);
        const double c12 = sanitize_d(red[tid][7] * invN - my * mz);
        const double c22 = sanitize_d(red[tid][8] * invN - mz * mz);
        // Matrix already symmetric; 0.5*(C + C^T) is the identity here.

        double emax, emin;
        const double p1 = c01 * c01 + c02 * c02 + c12 * c12;
        if (p1 == 0.0) {
            emax = fmax(c00, fmax(c11, c22));
            emin = fmin(c00, fmin(c11, c22));
        } else {
            const double q  = (c00 + c11 + c22) * (1.0 / 3.0);
            const double d0 = c00 - q, d1 = c11 - q, d2 = c22 - q;
            const double p2 = d0 * d0 + d1 * d1 + d2 * d2 + 2.0 * p1;
            const double p  = sqrt(p2 * (1.0 / 6.0));
            const double ip = 1.0 / p;
            const double b00 = d0 * ip, b11 = d1 * ip, b22 = d2 * ip;
            const double b01 = c01 * ip, b02 = c02 * ip, b12 = c12 * ip;
            double r = 0.5 * (b00 * (b11 * b22 - b12 * b12)
                            - b01 * (b01 * b22 - b12 * b02)
                            + b02 * (b01 * b12 - b11 * b02));
            r = fmin(1.0, fmax(-1.0, r));
            // Float transcendentals: error enters scaled by 2p (~1e-2) -> ~1e-8 abs.
            const float phi = acosf((float)r) * (1.0f / 3.0f);
            emax = q + 2.0 * p * (double)cosf(phi);
            emin = q + 2.0 * p * (double)cosf(phi + 2.0943951023931953f);
        }

        const double max_e = fmax(sanitize_d(emax), EPS_D);
        const double min_e = fmax(sanitize_d(emin), EPS_D);
        double ratio = max_e / min_e;
        ratio = fmin(MAX_RATIO_D, fmax(1.0, ratio));
        lr[b] = (double)logf((float)ratio);
    }
    __syncthreads();

    if (tid == 0) {
        double s = 0.0;
#pragma unroll
        for (int i = 0; i < B_BATCH; i++) s += lr[i];
        out[0] = (float)(-s * (1.0 / (double)B_BATCH));
    }
}

// ---------------------------------------------------------------------------
extern "C" void kernel_launch(void* const* d_in, const int* in_sizes, int n_in,
                              void* d_out, int out_size)
{
    (void)in_sizes; (void)n_in; (void)out_size;
    const float* gaussians = (const float*)d_in[0];
    float* out = (float*)d_out;

    dim3 grid(CHUNKS, B_BATCH);   // 32 x 32 = 1024 blocks, one full wave
    moments_kernel<<<grid, THREADS>>>(gaussians);
    finalize_kernel<<<1, THREADS>>>(out);
}